// round 8
// baseline (speedup 1.0000x reference)
#include <cuda_runtime.h>
#include <cstdint>
#include <cstddef>

// SNN Leaky scan. reset_t = H(mem_{t-1}-1); mem_t = beta*mem_{t-1}+x_t-reset_t; spk_t = H(mem_t-1)
// Heaviside via saturating FFMA (no predicate): r = fma.rn.sat(mem, 2^25, -2^25). Bit-exact
// vs reference for reachable mem range. Carried cycle: FFMA(4)->FADD(4), P = 8 cyc/step.
//
// KEY CHANGE vs R7: fully decoupled single-warp CTAs. 512 CTAs x 16 rows, 32 threads.
// One warp does everything (cp.async prefetch 2 chunks ahead, compute, coalesced STG)
// -> ZERO __syncthreads, ~3.5 independent pipelines per SM hiding each other's latency.

namespace {
constexpr int N_TOTAL  = 8192;
constexpr int T_STEPS  = 4000;
constexpr float BETA   = 0.95f;

constexpr int ROWS     = 16;     // rows per CTA (threads 0..15 compute, all 32 do io)
constexpr int THREADS  = 32;     // single warp
constexpr int TCHUNK   = 128;    // time steps per chunk
constexpr int TC4      = TCHUNK / 4;                          // 32 float4 per row-chunk
constexpr int NCHUNK   = (T_STEPS + TCHUNK - 1) / TCHUNK;     // 32 (31 full + 32-step tail)
constexpr int TAIL4    = (T_STEPS - (NCHUNK - 1) * TCHUNK) / 4;  // 8
constexpr int RSTRIDE  = TC4 + 1;                             // 33: odd stride, conflict-free
constexpr int BUFELEM  = ROWS * RSTRIDE;                      // 528 float4 per buffer
constexpr size_t SMEM_BYTES = (size_t)(3 + 1) * BUFELEM * sizeof(float4);  // ~33.8 KB
}

__device__ __forceinline__ void cp_async16(void* sdst, const void* gsrc) {
    uint32_t s = (uint32_t)__cvta_generic_to_shared(sdst);
    asm volatile("cp.async.cg.shared.global [%0], [%1], 16;" :: "r"(s), "l"(gsrc));
}
__device__ __forceinline__ void cp_commit() {
    asm volatile("cp.async.commit_group;" ::: "memory");
}
template <int NN>
__device__ __forceinline__ void cp_wait() {
    asm volatile("cp.async.wait_group %0;" :: "n"(NN) : "memory");
}

// Heaviside H(v - 1) as a single saturating FFMA (lat 4, fma pipe, no predicate).
__device__ __forceinline__ float heaviside_gt1(float v) {
    const float BIG = 33554432.0f;   // 2^25
    float r;
    asm("fma.rn.sat.f32 %0, %1, %2, %3;" : "=f"(r) : "f"(v), "f"(BIG), "f"(-BIG));
    return r;
}

// On entry r == reset_t (= spk_{t-1}); on exit r == spk_t. Carried cycle P = 8.
__device__ __forceinline__ void snn_step(float& mem, float& r, float x, float& spk) {
    float a = __fmaf_rn(BETA, mem, x);
    mem = a - r;              // exact: r in {0,1}
    r = heaviside_gt1(mem);
    spk = r;
}

__device__ __forceinline__ float4 snn_step4(float& mem, float& r, float4 x) {
    float4 s;
    snn_step(mem, r, x.x, s.x);
    snn_step(mem, r, x.y, s.y);
    snn_step(mem, r, x.z, s.z);
    snn_step(mem, r, x.w, s.w);
    return s;
}

__global__ void __launch_bounds__(THREADS, 6)
snn_leaky_sw_kernel(const float* __restrict__ inp, float* __restrict__ out) {
    extern __shared__ float4 smem[];
    const int lane = threadIdx.x & 31;
    const int rowBase = blockIdx.x * ROWS;

    float4* inbuf[3] = { smem, smem + BUFELEM, smem + 2 * BUFELEM };
    float4* outbuf   = smem + 3 * BUFELEM;

    // ---- prologue: preload chunks 0 and 1 (one commit group each) ----
    #pragma unroll
    for (int c0 = 0; c0 < 2; ++c0) {
        #pragma unroll
        for (int r = 0; r < ROWS; ++r) {
            const float4* g = reinterpret_cast<const float4*>(
                inp + (size_t)(rowBase + r) * T_STEPS + c0 * TCHUNK);
            cp_async16(&inbuf[c0][r * RSTRIDE + lane], g + lane);
        }
        cp_commit();
    }

    float mem = 0.0f, rst = 0.0f;

    for (int c = 0; c < NCHUNK; ++c) {
        cp_wait<1>();     // input chunk c landed (only the newest group may remain)
        __syncwarp();

        const int nv4 = (c == NCHUNK - 1) ? TAIL4 : TC4;

        // ---- compute: threads 0..15, one row each, spikes -> outbuf ----
        if (lane < ROWS) {
            const float4* __restrict__ rin  = inbuf[c % 3] + lane * RSTRIDE;
            float4* __restrict__       rout = outbuf + lane * RSTRIDE;
            if (c != NCHUNK - 1) {
                float4 xa = rin[0];            // LDS pipelined 2 iters ahead
                float4 xb = rin[1];
                #pragma unroll
                for (int t4 = 0; t4 < TC4; ++t4) {
                    float4 xc;
                    if (t4 + 2 < TC4) xc = rin[t4 + 2];
                    rout[t4] = snn_step4(mem, rst, xa);
                    xa = xb; xb = xc;
                }
            } else {
                float4 xa = rin[0];
                float4 xb = rin[1];
                #pragma unroll
                for (int t4 = 0; t4 < TAIL4; ++t4) {
                    float4 xc;
                    if (t4 + 2 < TAIL4) xc = rin[t4 + 2];
                    rout[t4] = snn_step4(mem, rst, xa);
                    xa = xb; xb = xc;
                }
            }
        }
        __syncwarp();     // make outbuf STS visible across lanes

        // ---- coalesced store of this chunk's spikes (all 32 lanes) ----
        if (lane < nv4) {
            #pragma unroll
            for (int r = 0; r < ROWS; ++r) {
                float4 v = outbuf[r * RSTRIDE + lane];
                reinterpret_cast<float4*>(
                    out + (size_t)(rowBase + r) * T_STEPS + c * TCHUNK)[lane] = v;
            }
        }

        // ---- prefetch input chunk c+2 ----
        if (c + 2 < NCHUNK) {
            const int cn = c + 2;
            const int nvn = (cn == NCHUNK - 1) ? TAIL4 : TC4;
            float4* b = inbuf[cn % 3];
            if (lane < nvn) {
                #pragma unroll
                for (int r = 0; r < ROWS; ++r) {
                    const float4* g = reinterpret_cast<const float4*>(
                        inp + (size_t)(rowBase + r) * T_STEPS + cn * TCHUNK);
                    cp_async16(&b[r * RSTRIDE + lane], g + lane);
                }
            }
        }
        cp_commit();      // unconditional: uniform group counting
        __syncwarp();     // outbuf fully consumed before next compute overwrites it
    }
}

extern "C" void kernel_launch(void* const* d_in, const int* in_sizes, int n_in,
                              void* d_out, int out_size) {
    (void)in_sizes; (void)n_in; (void)out_size;
    const float* inp = (const float*)d_in[0];
    float* out = (float*)d_out;

    cudaFuncSetAttribute(snn_leaky_sw_kernel,
                         cudaFuncAttributeMaxDynamicSharedMemorySize,
                         (int)SMEM_BYTES);
    snn_leaky_sw_kernel<<<N_TOTAL / ROWS, THREADS, SMEM_BYTES>>>(inp, out);
}